// round 6
// baseline (speedup 1.0000x reference)
#include <cuda_runtime.h>
#include <cuda_bf16.h>
#include <cstdint>

#define B_N 2048
#define H_N 4096
#define E_N 8
#define L_N 512

// ---------------- scratch ----------------
__device__ int   g_counts[E_N];
__device__ int   g_rows[E_N][B_N];
__device__ float g_pen[25];

__device__ __align__(256) __nv_bfloat16 g_hid_hi[B_N * H_N];
__device__ __align__(256) __nv_bfloat16 g_hid_lo[B_N * H_N];
__device__ __align__(256) __nv_bfloat16 g_W_hi[E_N * L_N * H_N];
__device__ __align__(256) __nv_bfloat16 g_W_lo[E_N * L_N * H_N];

__global__ void init_kernel() {
    int t = threadIdx.x;
    if (t < E_N) g_counts[t] = 0;
    if (t < 25)  g_pen[t]    = 0.0f;
}

// ---------------- expert selection ----------------
__global__ void select_kernel(const float* __restrict__ envs,
                              const int* __restrict__ idx32,
                              const float* __restrict__ gumbel) {
    int b = blockIdx.x * blockDim.x + threadIdx.x;
    if (b >= B_N) return;
    int stride = (idx32[1] == 0) ? 2 : 1;   // int64-on-disk detection (idx = arange)
    int r = idx32[(size_t)b * stride];
    if (r < 0) r = 0;
    if (r >= B_N) r = B_N - 1;
    const float* ev = envs   + (size_t)r * E_N;
    const float* gv = gumbel + (size_t)b * E_N;
    float best = ev[0] + gv[0];
    int be = 0;
#pragma unroll
    for (int e = 1; e < E_N; e++) {
        float v = ev[e] + gv[e];
        if (v > best) { best = v; be = e; }
    }
    int pos = atomicAdd(&g_counts[be], 1);
    g_rows[be][pos] = b;
}

// ---------------- fp32 -> bf16 hi/lo split ----------------
__device__ __forceinline__ void split4(float4 v, uint2& ph, uint2& pl) {
    __nv_bfloat162 h01 = __floats2bfloat162_rn(v.x, v.y);
    __nv_bfloat162 h23 = __floats2bfloat162_rn(v.z, v.w);
    __nv_bfloat162 l01 = __floats2bfloat162_rn(v.x - __bfloat162float(h01.x),
                                               v.y - __bfloat162float(h01.y));
    __nv_bfloat162 l23 = __floats2bfloat162_rn(v.z - __bfloat162float(h23.x),
                                               v.w - __bfloat162float(h23.y));
    ph.x = *reinterpret_cast<uint32_t*>(&h01);
    ph.y = *reinterpret_cast<uint32_t*>(&h23);
    pl.x = *reinterpret_cast<uint32_t*>(&l01);
    pl.y = *reinterpret_cast<uint32_t*>(&l23);
}

__global__ void __launch_bounds__(256)
convert_hidden_kernel(const float* __restrict__ hidden) {
    const int n4 = B_N * H_N / 4;
    const float4* hv = (const float4*)hidden;
    uint2* hh = (uint2*)g_hid_hi;
    uint2* hl = (uint2*)g_hid_lo;
    int stride = gridDim.x * blockDim.x;
    for (int i = blockIdx.x * blockDim.x + threadIdx.x; i < n4; i += stride) {
        uint2 ph, pl;
        split4(hv[i], ph, pl);
        hh[i] = ph;
        hl[i] = pl;
    }
}

// ---------------- penalty + W -> bf16 hi/lo (fused single pass) ----------------
__global__ void __launch_bounds__(256)
penalty_kernel(const float* __restrict__ W) {
    const int LH4 = (L_N * H_N) / 4;
    const float4* Wv = (const float4*)W;
    uint2* wh = (uint2*)g_W_hi;
    uint2* wl = (uint2*)g_W_lo;

    float q[8], c[8], l1[8], ss = 0.0f;
#pragma unroll
    for (int e = 0; e < 8; e++) { q[e] = 0.f; c[e] = 0.f; l1[e] = 0.f; }

    int stride = gridDim.x * blockDim.x;
    for (int i = blockIdx.x * blockDim.x + threadIdx.x; i < LH4; i += stride) {
        float4 w[8];
#pragma unroll
        for (int e = 0; e < 8; e++) w[e] = Wv[(size_t)e * LH4 + i];
#pragma unroll
        for (int e = 0; e < 8; e++) {
            uint2 ph, pl;
            split4(w[e], ph, pl);
            wh[(size_t)e * LH4 + i] = ph;
            wl[(size_t)e * LH4 + i] = pl;
        }
#pragma unroll
        for (int comp = 0; comp < 4; comp++) {
            float we[8];
#pragma unroll
            for (int e = 0; e < 8; e++) {
                float4 t = w[e];
                we[e] = (comp == 0) ? t.x : (comp == 1) ? t.y : (comp == 2) ? t.z : t.w;
            }
            float s = 0.f;
#pragma unroll
            for (int e = 0; e < 8; e++) s += we[e];
            ss = fmaf(s, s, ss);
#pragma unroll
            for (int e = 0; e < 8; e++) {
                q[e]  = fmaf(we[e], we[e], q[e]);
                c[e]  = fmaf(we[e], s,     c[e]);
                l1[e] += fabsf(we[e]);
            }
        }
    }

    __shared__ float red[25][264];
    int tid = threadIdx.x;
#pragma unroll
    for (int e = 0; e < 8; e++) {
        red[e][tid]      = q[e];
        red[8 + e][tid]  = c[e];
        red[16 + e][tid] = l1[e];
    }
    red[24][tid] = ss;
    __syncthreads();
    if (tid < 25) {
        float s = 0.f;
#pragma unroll 8
        for (int j = 0; j < 256; j++) s += red[tid][j];
        atomicAdd(&g_pen[tid], s);
    }
}

__global__ void finalize_kernel(float* __restrict__ pen_out) {
    if (threadIdx.x == 0) {
        float acc = 0.f;
        float ss = g_pen[24];
#pragma unroll
        for (int e = 0; e < 8; e++) {
            float diff = g_pen[e] - 0.25f * g_pen[8 + e] + ss * (1.0f / 64.0f);
            float l1 = g_pen[16 + e];
            acc += diff / (l1 * l1);
        }
        pen_out[0] = acc * 0.125f;
    }
}

// =========== tensor-core grouped GEMM (mma.sync, 3-stage cp.async) ===========
// CTA tile 128(M) x 64(N) x 64(K); 256 threads = 8 warps (4M x 2N), warp 32x32.
// Stage layout (bytes): AH 16K | AL 16K | BH 8K | BL 8K = 48KB; 3 stages = 144KB.
// Swizzle: row stride 64 halves (128B), 16B chunk phys = chunk ^ (row & 7).

#define TM 128
#define TN 64
#define TK 64
#define NSTAGE 3
#define STG_B 49152
#define NIT (H_N / TK)          // 64
#define GRID_Y 2
#define SMEM_DYN (NSTAGE * STG_B + 1024)

static __device__ __forceinline__ uint32_t s2u(const void* p) {
    return (uint32_t)__cvta_generic_to_shared(p);
}
static __device__ __forceinline__ void cp16(uint32_t s, const __nv_bfloat16* g, bool pred) {
    int sz = pred ? 16 : 0;
    asm volatile("cp.async.cg.shared.global [%0], [%1], 16, %2;"
                 :: "r"(s), "l"(g), "r"(sz));
}

#define LDSM4(r0, r1, r2, r3, a) \
    asm volatile("ldmatrix.sync.aligned.m8n8.x4.shared.b16 {%0,%1,%2,%3}, [%4];" \
                 : "=r"(r0), "=r"(r1), "=r"(r2), "=r"(r3) : "r"(a))

#define MMA16816(d, A, b0, b1) \
    asm volatile("mma.sync.aligned.m16n8k16.row.col.f32.bf16.bf16.f32 " \
                 "{%0,%1,%2,%3}, {%4,%5,%6,%7}, {%8,%9}, {%0,%1,%2,%3};" \
                 : "+f"((d)[0]), "+f"((d)[1]), "+f"((d)[2]), "+f"((d)[3]) \
                 : "r"((A)[0]), "r"((A)[1]), "r"((A)[2]), "r"((A)[3]), \
                   "r"(b0), "r"(b1))

extern __shared__ char dyn_raw[];

__global__ void __launch_bounds__(256, 1)
gemm_kernel(float* __restrict__ out) {
    __shared__ int rowids[TM];

    int e = blockIdx.z;
    int cnt = g_counts[e];
    if (blockIdx.y * TM >= cnt) return;
    int l_base = blockIdx.x * TN;
    int tid = threadIdx.x;
    int wid = tid >> 5, lane = tid & 31;

    uint32_t sbase = (s2u(dyn_raw) + 1023) & ~1023u;
    uint32_t stb[NSTAGE];
#pragma unroll
    for (int s = 0; s < NSTAGE; s++) stb[s] = sbase + s * STG_B;

    // loader geometry: 16B chunks, phys chunk = chunk ^ (row & 7)
    int lrow = tid >> 3;              // 0..31
    int lcc  = tid & 7;
    int lphys = lcc ^ (lrow & 7);
    int sA[4], sB[2];
#pragma unroll
    for (int i = 0; i < 4; i++) sA[i] = ((lrow + i * 32) * 64 + lphys * 8) * 2;  // bytes
#pragma unroll
    for (int i = 0; i < 2; i++) sB[i] = ((lrow + i * 32) * 64 + lphys * 8) * 2;

    const __nv_bfloat16* gBh[2];
    const __nv_bfloat16* gBl[2];
#pragma unroll
    for (int i = 0; i < 2; i++) {
        size_t off = ((size_t)e * L_N + l_base + lrow + i * 32) * H_N + lcc * 8;
        gBh[i] = g_W_hi + off;
        gBl[i] = g_W_lo + off;
    }

    // warp geometry
    int wm = (wid & 3) * 32;
    int wn = (wid >> 2) * 32;
    int a_r = lane & 15, a_h = lane >> 4;
    int b_g = lane >> 3, b_sub = b_g >> 1, b_h = b_g & 1, b_r = lane & 7;

    int arow[2], axr[2];
#pragma unroll
    for (int mt = 0; mt < 2; mt++) {
        int r = wm + mt * 16 + a_r;
        arow[mt] = r * 64; axr[mt] = r & 7;
    }
    int brow[2], bxr[2];
#pragma unroll
    for (int p = 0; p < 2; p++) {
        int r = wn + p * 16 + b_sub * 8 + b_r;
        brow[p] = r * 64; bxr[p] = r & 7;
    }
    int gid = lane >> 2, tig = lane & 3;

    for (int mb = blockIdx.y; mb * TM < cnt; mb += GRID_Y) {
        if (tid < TM) {
            int i = mb * TM + tid;
            rowids[tid] = (i < cnt) ? g_rows[e][i] : -1;
        }
        __syncthreads();

        const __nv_bfloat16* gAh[4];
        const __nv_bfloat16* gAl[4];
        bool apred[4];
#pragma unroll
        for (int i = 0; i < 4; i++) {
            int g = rowids[lrow + i * 32];
            apred[i] = (g >= 0);
            size_t off = (size_t)(apred[i] ? g : 0) * H_N + lcc * 8;
            gAh[i] = g_hid_hi + off;
            gAl[i] = g_hid_lo + off;
        }

        float acc[2][4][4];
#pragma unroll
        for (int mt = 0; mt < 2; mt++)
#pragma unroll
            for (int nt = 0; nt < 4; nt++)
#pragma unroll
                for (int j = 0; j < 4; j++) acc[mt][nt][j] = 0.f;

        // preload stages 0,1
#pragma unroll
        for (int p = 0; p < 2; p++) {
            uint32_t b = stb[p];
            int koff = p * TK;
#pragma unroll
            for (int i = 0; i < 4; i++) {
                cp16(b + sA[i], gAh[i] + koff, apred[i]);
                cp16(b + 16384 + sA[i], gAl[i] + koff, apred[i]);
            }
#pragma unroll
            for (int i = 0; i < 2; i++) {
                cp16(b + 32768 + sB[i], gBh[i] + koff, true);
                cp16(b + 40960 + sB[i], gBl[i] + koff, true);
            }
            asm volatile("cp.async.commit_group;");
        }

        int cur = 0, nxt = 2;
        for (int it = 0; it < NIT; it++) {
            asm volatile("cp.async.wait_group 1;");
            __syncthreads();

            // prefetch stage it+2 (safe: all warps past barrier -> done with it-1)
            int nc = it + 2;
            if (nc < NIT) {
                uint32_t b = stb[nxt];
                int koff = nc * TK;
#pragma unroll
                for (int i = 0; i < 4; i++) {
                    cp16(b + sA[i], gAh[i] + koff, apred[i]);
                    cp16(b + 16384 + sA[i], gAl[i] + koff, apred[i]);
                }
#pragma unroll
                for (int i = 0; i < 2; i++) {
                    cp16(b + 32768 + sB[i], gBh[i] + koff, true);
                    cp16(b + 40960 + sB[i], gBl[i] + koff, true);
                }
            }
            asm volatile("cp.async.commit_group;");

            uint32_t AH = stb[cur];
            uint32_t AL = AH + 16384;
            uint32_t BH = AH + 32768;
            uint32_t BL = AH + 40960;

#pragma unroll
            for (int s4 = 0; s4 < 4; s4++) {
                uint32_t ah[2][4], al[2][4], bh[4][2], bl[4][2];
#pragma unroll
                for (int mt = 0; mt < 2; mt++) {
                    int ch = (2 * s4 + a_h) ^ axr[mt];
                    LDSM4(ah[mt][0], ah[mt][1], ah[mt][2], ah[mt][3],
                          AH + (arow[mt] + ch * 8) * 2);
                    LDSM4(al[mt][0], al[mt][1], al[mt][2], al[mt][3],
                          AL + (arow[mt] + ch * 8) * 2);
                }
#pragma unroll
                for (int p = 0; p < 2; p++) {
                    int ch = (2 * s4 + b_h) ^ bxr[p];
                    uint32_t r0, r1, r2, r3;
                    LDSM4(r0, r1, r2, r3, BH + (brow[p] + ch * 8) * 2);
                    bh[2 * p][0] = r0; bh[2 * p][1] = r1;
                    bh[2 * p + 1][0] = r2; bh[2 * p + 1][1] = r3;
                    LDSM4(r0, r1, r2, r3, BL + (brow[p] + ch * 8) * 2);
                    bl[2 * p][0] = r0; bl[2 * p][1] = r1;
                    bl[2 * p + 1][0] = r2; bl[2 * p + 1][1] = r3;
                }
                // product-major ordering: 8 independent MMAs between touches of
                // the same accumulator
#pragma unroll
                for (int mt = 0; mt < 2; mt++)
#pragma unroll
                    for (int nt = 0; nt < 4; nt++)
                        MMA16816(acc[mt][nt], ah[mt], bh[nt][0], bh[nt][1]);
#pragma unroll
                for (int mt = 0; mt < 2; mt++)
#pragma unroll
                    for (int nt = 0; nt < 4; nt++)
                        MMA16816(acc[mt][nt], ah[mt], bl[nt][0], bl[nt][1]);
#pragma unroll
                for (int mt = 0; mt < 2; mt++)
#pragma unroll
                    for (int nt = 0; nt < 4; nt++)
                        MMA16816(acc[mt][nt], al[mt], bh[nt][0], bh[nt][1]);
            }
            cur = (cur + 1 == NSTAGE) ? 0 : cur + 1;
            nxt = (nxt + 1 == NSTAGE) ? 0 : nxt + 1;
        }

        // ---- epilogue ----
#pragma unroll
        for (int mt = 0; mt < 2; mt++) {
            int r0 = wm + mt * 16 + gid;
            int r1 = r0 + 8;
            int g0 = rowids[r0];
            int g1 = rowids[r1];
#pragma unroll
            for (int nt = 0; nt < 4; nt++) {
                int col = l_base + wn + nt * 8 + tig * 2;
                if (g0 >= 0)
                    *(float2*)(out + (size_t)g0 * L_N + col) =
                        make_float2(acc[mt][nt][0], acc[mt][nt][1]);
                if (g1 >= 0)
                    *(float2*)(out + (size_t)g1 * L_N + col) =
                        make_float2(acc[mt][nt][2], acc[mt][nt][3]);
            }
        }
        __syncthreads();   // rowids stable until all warps done
    }
}

// ---------------- launch ----------------
extern "C" void kernel_launch(void* const* d_in, const int* in_sizes, int n_in,
                              void* d_out, int out_size) {
    const float* hidden = (const float*)d_in[0];
    const float* envs   = (const float*)d_in[1];
    const int*   idx32  = (const int*)d_in[2];
    const float* gumbel = (const float*)d_in[3];
    const float* W      = (const float*)d_in[4];
    float* out = (float*)d_out;

    cudaFuncSetAttribute(gemm_kernel,
                         cudaFuncAttributeMaxDynamicSharedMemorySize, SMEM_DYN);

    init_kernel<<<1, 32>>>();
    select_kernel<<<(B_N + 255) / 256, 256>>>(envs, idx32, gumbel);
    convert_hidden_kernel<<<1024, 256>>>(hidden);
    penalty_kernel<<<512, 256>>>(W);

    dim3 ggrid(L_N / TN, GRID_Y, E_N);
    gemm_kernel<<<ggrid, 256, SMEM_DYN>>>(out);

    if (out_size > B_N * L_N)
        finalize_kernel<<<1, 32>>>(out + (size_t)B_N * L_N);
}

// round 7
// speedup vs baseline: 1.5339x; 1.5339x over previous
#include <cuda_runtime.h>
#include <cuda_bf16.h>
#include <cstdint>

#define B_N 2048
#define H_N 4096
#define E_N 8
#define L_N 512

// ---------------- scratch ----------------
__device__ int   g_counts[E_N];
__device__ int   g_rows[E_N][B_N];
__device__ float g_pen[25];
__device__ int   g_ntiles;
__device__ int   g_tile_ctr;
__device__ uint32_t g_tiles[512];

__device__ __align__(256) __nv_bfloat16 g_hid_hi[B_N * H_N];
__device__ __align__(256) __nv_bfloat16 g_hid_lo[B_N * H_N];
__device__ __align__(256) __nv_bfloat16 g_W_hi[E_N * L_N * H_N];
__device__ __align__(256) __nv_bfloat16 g_W_lo[E_N * L_N * H_N];

__global__ void init_kernel() {
    int t = threadIdx.x;
    if (t < E_N) g_counts[t] = 0;
    if (t < 25)  g_pen[t]    = 0.0f;
    if (t == 0)  g_tile_ctr  = 0;
}

// ---------------- expert selection ----------------
__global__ void select_kernel(const float* __restrict__ envs,
                              const int* __restrict__ idx32,
                              const float* __restrict__ gumbel) {
    int b = blockIdx.x * blockDim.x + threadIdx.x;
    if (b >= B_N) return;
    int stride = (idx32[1] == 0) ? 2 : 1;   // int64-on-disk detection (idx = arange)
    int r = idx32[(size_t)b * stride];
    if (r < 0) r = 0;
    if (r >= B_N) r = B_N - 1;
    const float* ev = envs   + (size_t)r * E_N;
    const float* gv = gumbel + (size_t)b * E_N;
    float best = ev[0] + gv[0];
    int be = 0;
#pragma unroll
    for (int e = 1; e < E_N; e++) {
        float v = ev[e] + gv[e];
        if (v > best) { best = v; be = e; }
    }
    int pos = atomicAdd(&g_counts[be], 1);
    g_rows[be][pos] = b;
}

// ---------------- balanced tile list ----------------
// tile = (expert, 64-row m-chunk, 64-col l-block); enc = e<<12 | m<<4 | l
__global__ void build_tiles_kernel() {
    if (threadIdx.x == 0) {
        int n = 0;
        for (int e = 0; e < E_N; e++) {
            int mc = (g_counts[e] + 63) >> 6;
            for (int m = 0; m < mc; m++)
                for (int l = 0; l < 8; l++)
                    g_tiles[n++] = (e << 12) | (m << 4) | l;
        }
        g_ntiles = n;
    }
}

// ---------------- fp32 -> bf16 hi/lo split ----------------
__device__ __forceinline__ void split4(float4 v, uint2& ph, uint2& pl) {
    __nv_bfloat162 h01 = __floats2bfloat162_rn(v.x, v.y);
    __nv_bfloat162 h23 = __floats2bfloat162_rn(v.z, v.w);
    __nv_bfloat162 l01 = __floats2bfloat162_rn(v.x - __bfloat162float(h01.x),
                                               v.y - __bfloat162float(h01.y));
    __nv_bfloat162 l23 = __floats2bfloat162_rn(v.z - __bfloat162float(h23.x),
                                               v.w - __bfloat162float(h23.y));
    ph.x = *reinterpret_cast<uint32_t*>(&h01);
    ph.y = *reinterpret_cast<uint32_t*>(&h23);
    pl.x = *reinterpret_cast<uint32_t*>(&l01);
    pl.y = *reinterpret_cast<uint32_t*>(&l23);
}

__global__ void __launch_bounds__(256)
convert_hidden_kernel(const float* __restrict__ hidden) {
    const int n4 = B_N * H_N / 4;
    const float4* hv = (const float4*)hidden;
    uint2* hh = (uint2*)g_hid_hi;
    uint2* hl = (uint2*)g_hid_lo;
    int stride = gridDim.x * blockDim.x;
    for (int i = blockIdx.x * blockDim.x + threadIdx.x; i < n4; i += stride) {
        uint2 ph, pl;
        split4(hv[i], ph, pl);
        hh[i] = ph;
        hl[i] = pl;
    }
}

// ---------------- penalty + W -> bf16 hi/lo (fused single pass) ----------------
__global__ void __launch_bounds__(256)
penalty_kernel(const float* __restrict__ W) {
    const int LH4 = (L_N * H_N) / 4;
    const float4* Wv = (const float4*)W;
    uint2* wh = (uint2*)g_W_hi;
    uint2* wl = (uint2*)g_W_lo;

    float q[8], c[8], l1[8], ss = 0.0f;
#pragma unroll
    for (int e = 0; e < 8; e++) { q[e] = 0.f; c[e] = 0.f; l1[e] = 0.f; }

    int stride = gridDim.x * blockDim.x;
    for (int i = blockIdx.x * blockDim.x + threadIdx.x; i < LH4; i += stride) {
        float4 w[8];
#pragma unroll
        for (int e = 0; e < 8; e++) w[e] = Wv[(size_t)e * LH4 + i];
#pragma unroll
        for (int e = 0; e < 8; e++) {
            uint2 ph, pl;
            split4(w[e], ph, pl);
            wh[(size_t)e * LH4 + i] = ph;
            wl[(size_t)e * LH4 + i] = pl;
        }
#pragma unroll
        for (int comp = 0; comp < 4; comp++) {
            float we[8];
#pragma unroll
            for (int e = 0; e < 8; e++) {
                float4 t = w[e];
                we[e] = (comp == 0) ? t.x : (comp == 1) ? t.y : (comp == 2) ? t.z : t.w;
            }
            float s = 0.f;
#pragma unroll
            for (int e = 0; e < 8; e++) s += we[e];
            ss = fmaf(s, s, ss);
#pragma unroll
            for (int e = 0; e < 8; e++) {
                q[e]  = fmaf(we[e], we[e], q[e]);
                c[e]  = fmaf(we[e], s,     c[e]);
                l1[e] += fabsf(we[e]);
            }
        }
    }

    __shared__ float red[25][264];
    int tid = threadIdx.x;
#pragma unroll
    for (int e = 0; e < 8; e++) {
        red[e][tid]      = q[e];
        red[8 + e][tid]  = c[e];
        red[16 + e][tid] = l1[e];
    }
    red[24][tid] = ss;
    __syncthreads();
    if (tid < 25) {
        float s = 0.f;
#pragma unroll 8
        for (int j = 0; j < 256; j++) s += red[tid][j];
        atomicAdd(&g_pen[tid], s);
    }
}

__global__ void finalize_kernel(float* __restrict__ pen_out) {
    if (threadIdx.x == 0) {
        float acc = 0.f;
        float ss = g_pen[24];
#pragma unroll
        for (int e = 0; e < 8; e++) {
            float diff = g_pen[e] - 0.25f * g_pen[8 + e] + ss * (1.0f / 64.0f);
            float l1 = g_pen[16 + e];
            acc += diff / (l1 * l1);
        }
        pen_out[0] = acc * 0.125f;
    }
}

// ====== persistent tensor-core grouped GEMM (balanced tile queue) ======
// CTA tile 64(M) x 64(N) x 64(K); 128 threads = 4 warps (2M x 2N), warp 32x32.
// Stage (bytes): AH 8K | AL 8K | BH 8K | BL 8K = 32KB; 3 stages = 96KB; 2 CTA/SM.
// Swizzle: row stride 64 halves (128B), 16B chunk phys = chunk ^ (row & 7).

#define TMB 64
#define TNB 64
#define TK 64
#define NSTAGE 3
#define STG_B 32768
#define NIT (H_N / TK)          // 64
#define SMEM_DYN (NSTAGE * STG_B + 1024)
#define GRID_GEMM 296

static __device__ __forceinline__ uint32_t s2u(const void* p) {
    return (uint32_t)__cvta_generic_to_shared(p);
}
static __device__ __forceinline__ void cp16(uint32_t s, const __nv_bfloat16* g, bool pred) {
    int sz = pred ? 16 : 0;
    asm volatile("cp.async.cg.shared.global [%0], [%1], 16, %2;"
                 :: "r"(s), "l"(g), "r"(sz));
}

#define LDSM4(r0, r1, r2, r3, a) \
    asm volatile("ldmatrix.sync.aligned.m8n8.x4.shared.b16 {%0,%1,%2,%3}, [%4];" \
                 : "=r"(r0), "=r"(r1), "=r"(r2), "=r"(r3) : "r"(a))

#define MMA16816(d, A, b0, b1) \
    asm volatile("mma.sync.aligned.m16n8k16.row.col.f32.bf16.bf16.f32 " \
                 "{%0,%1,%2,%3}, {%4,%5,%6,%7}, {%8,%9}, {%0,%1,%2,%3};" \
                 : "+f"((d)[0]), "+f"((d)[1]), "+f"((d)[2]), "+f"((d)[3]) \
                 : "r"((A)[0]), "r"((A)[1]), "r"((A)[2]), "r"((A)[3]), \
                   "r"(b0), "r"(b1))

extern __shared__ char dyn_raw[];

__global__ void __launch_bounds__(128, 2)
gemm_kernel(float* __restrict__ out) {
    __shared__ int rowids[TMB];
    __shared__ int s_tile;

    int tid = threadIdx.x;
    int wid = tid >> 5, lane = tid & 31;

    uint32_t sbase = (s2u(dyn_raw) + 1023) & ~1023u;
    uint32_t stb[NSTAGE];
#pragma unroll
    for (int s = 0; s < NSTAGE; s++) stb[s] = sbase + s * STG_B;

    // loader geometry: 512 16B slots per tensor-half, 4 per thread
    int lrow = tid >> 3;              // 0..15; actual rows lrow + 16*i
    int lcc  = tid & 7;
    int lphys = lcc ^ (lrow & 7);     // row&7 invariant across i (16 % 8 == 0)
    int sOff[4];
#pragma unroll
    for (int i = 0; i < 4; i++) sOff[i] = ((lrow + i * 16) * 64 + lphys * 8) * 2;  // bytes

    // warp geometry (32x32 warp tile)
    int wm = (wid & 1) * 32;
    int wn = (wid >> 1) * 32;
    int a_r = lane & 15, a_h = lane >> 4;
    int b_g = lane >> 3, b_sub = b_g >> 1, b_h = b_g & 1, b_r = lane & 7;

    int arow[2], axr[2];
#pragma unroll
    for (int mt = 0; mt < 2; mt++) {
        int r = wm + mt * 16 + a_r;
        arow[mt] = r * 64; axr[mt] = r & 7;
    }
    int brow[2], bxr[2];
#pragma unroll
    for (int p = 0; p < 2; p++) {
        int r = wn + p * 16 + b_sub * 8 + b_r;
        brow[p] = r * 64; bxr[p] = r & 7;
    }
    int gid = lane >> 2, tig = lane & 3;

    for (;;) {
        __syncthreads();   // previous tile fully done (rowids/s_tile reusable)
        if (tid == 0) s_tile = atomicAdd(&g_tile_ctr, 1);
        __syncthreads();
        int t = s_tile;
        if (t >= g_ntiles) break;

        uint32_t enc = g_tiles[t];
        int e = enc >> 12;
        int mch = (enc >> 4) & 255;
        int l_base = (enc & 15) * TNB;
        int cnt = g_counts[e];

        if (tid < TMB) {
            int i = mch * TMB + tid;
            rowids[tid] = (i < cnt) ? g_rows[e][i] : -1;
        }
        __syncthreads();

        const __nv_bfloat16* gAh[4];
        const __nv_bfloat16* gAl[4];
        const __nv_bfloat16* gBh[4];
        const __nv_bfloat16* gBl[4];
        bool apred[4];
#pragma unroll
        for (int i = 0; i < 4; i++) {
            int row = lrow + i * 16;
            int g = rowids[row];
            apred[i] = (g >= 0);
            size_t aoff = (size_t)(apred[i] ? g : 0) * H_N + lcc * 8;
            gAh[i] = g_hid_hi + aoff;
            gAl[i] = g_hid_lo + aoff;
            size_t boff = ((size_t)e * L_N + l_base + row) * H_N + lcc * 8;
            gBh[i] = g_W_hi + boff;
            gBl[i] = g_W_lo + boff;
        }

        float acc[2][4][4];
#pragma unroll
        for (int mt = 0; mt < 2; mt++)
#pragma unroll
            for (int nt = 0; nt < 4; nt++)
#pragma unroll
                for (int j = 0; j < 4; j++) acc[mt][nt][j] = 0.f;

        // preload stages 0,1
#pragma unroll
        for (int p = 0; p < 2; p++) {
            uint32_t b = stb[p];
            int koff = p * TK;
#pragma unroll
            for (int i = 0; i < 4; i++) {
                cp16(b + sOff[i], gAh[i] + koff, apred[i]);
                cp16(b + 8192 + sOff[i], gAl[i] + koff, apred[i]);
                cp16(b + 16384 + sOff[i], gBh[i] + koff, true);
                cp16(b + 24576 + sOff[i], gBl[i] + koff, true);
            }
            asm volatile("cp.async.commit_group;");
        }

        int cur = 0, nxt = 2;
        for (int it = 0; it < NIT; it++) {
            asm volatile("cp.async.wait_group 1;");
            __syncthreads();

            int nc = it + 2;
            if (nc < NIT) {
                uint32_t b = stb[nxt];
                int koff = nc * TK;
#pragma unroll
                for (int i = 0; i < 4; i++) {
                    cp16(b + sOff[i], gAh[i] + koff, apred[i]);
                    cp16(b + 8192 + sOff[i], gAl[i] + koff, apred[i]);
                    cp16(b + 16384 + sOff[i], gBh[i] + koff, true);
                    cp16(b + 24576 + sOff[i], gBl[i] + koff, true);
                }
            }
            asm volatile("cp.async.commit_group;");

            uint32_t AH = stb[cur];
            uint32_t AL = AH + 8192;
            uint32_t BH = AH + 16384;
            uint32_t BL = AH + 24576;

#pragma unroll
            for (int s4 = 0; s4 < 4; s4++) {
                uint32_t ah[2][4], al[2][4], bh[4][2], bl[4][2];
#pragma unroll
                for (int mt = 0; mt < 2; mt++) {
                    int ch = (2 * s4 + a_h) ^ axr[mt];
                    LDSM4(ah[mt][0], ah[mt][1], ah[mt][2], ah[mt][3],
                          AH + (arow[mt] + ch * 8) * 2);
                    LDSM4(al[mt][0], al[mt][1], al[mt][2], al[mt][3],
                          AL + (arow[mt] + ch * 8) * 2);
                }
#pragma unroll
                for (int p = 0; p < 2; p++) {
                    int ch = (2 * s4 + b_h) ^ bxr[p];
                    uint32_t r0, r1, r2, r3;
                    LDSM4(r0, r1, r2, r3, BH + (brow[p] + ch * 8) * 2);
                    bh[2 * p][0] = r0; bh[2 * p][1] = r1;
                    bh[2 * p + 1][0] = r2; bh[2 * p + 1][1] = r3;
                    LDSM4(r0, r1, r2, r3, BL + (brow[p] + ch * 8) * 2);
                    bl[2 * p][0] = r0; bl[2 * p][1] = r1;
                    bl[2 * p + 1][0] = r2; bl[2 * p + 1][1] = r3;
                }
                // product-major: 8 independent MMAs between same-acc touches
#pragma unroll
                for (int mt = 0; mt < 2; mt++)
#pragma unroll
                    for (int nt = 0; nt < 4; nt++)
                        MMA16816(acc[mt][nt], ah[mt], bh[nt][0], bh[nt][1]);
#pragma unroll
                for (int mt = 0; mt < 2; mt++)
#pragma unroll
                    for (int nt = 0; nt < 4; nt++)
                        MMA16816(acc[mt][nt], ah[mt], bl[nt][0], bl[nt][1]);
#pragma unroll
                for (int mt = 0; mt < 2; mt++)
#pragma unroll
                    for (int nt = 0; nt < 4; nt++)
                        MMA16816(acc[mt][nt], al[mt], bh[nt][0], bh[nt][1]);
            }
            cur = (cur + 1 == NSTAGE) ? 0 : cur + 1;
            nxt = (nxt + 1 == NSTAGE) ? 0 : nxt + 1;
        }

        // ---- epilogue ----
#pragma unroll
        for (int mt = 0; mt < 2; mt++) {
            int r0 = wm + mt * 16 + gid;
            int r1 = r0 + 8;
            int g0 = rowids[r0];
            int g1 = rowids[r1];
#pragma unroll
            for (int nt = 0; nt < 4; nt++) {
                int col = l_base + wn + nt * 8 + tig * 2;
                if (g0 >= 0)
                    *(float2*)(out + (size_t)g0 * L_N + col) =
                        make_float2(acc[mt][nt][0], acc[mt][nt][1]);
                if (g1 >= 0)
                    *(float2*)(out + (size_t)g1 * L_N + col) =
                        make_float2(acc[mt][nt][2], acc[mt][nt][3]);
            }
        }
    }
}

// ---------------- launch ----------------
extern "C" void kernel_launch(void* const* d_in, const int* in_sizes, int n_in,
                              void* d_out, int out_size) {
    const float* hidden = (const float*)d_in[0];
    const float* envs   = (const float*)d_in[1];
    const int*   idx32  = (const int*)d_in[2];
    const float* gumbel = (const float*)d_in[3];
    const float* W      = (const float*)d_in[4];
    float* out = (float*)d_out;

    cudaFuncSetAttribute(gemm_kernel,
                         cudaFuncAttributeMaxDynamicSharedMemorySize, SMEM_DYN);

    init_kernel<<<1, 32>>>();
    select_kernel<<<(B_N + 255) / 256, 256>>>(envs, idx32, gumbel);
    build_tiles_kernel<<<1, 32>>>();
    convert_hidden_kernel<<<1024, 256>>>(hidden);
    penalty_kernel<<<512, 256>>>(W);

    gemm_kernel<<<GRID_GEMM, 128, SMEM_DYN>>>(out);

    if (out_size > B_N * L_N)
        finalize_kernel<<<1, 32>>>(out + (size_t)B_N * L_N);
}

// round 8
// speedup vs baseline: 1.9957x; 1.3011x over previous
#include <cuda_runtime.h>
#include <cuda_fp16.h>
#include <cstdint>

#define B_N 2048
#define H_N 4096
#define E_N 8
#define L_N 512

// ---------------- scratch ----------------
__device__ int   g_counts[E_N];
__device__ int   g_rows[E_N][B_N];
__device__ float g_pen[25];
__device__ int   g_ntiles;
__device__ int   g_tile_ctr;
__device__ uint32_t g_tiles[512];

__device__ __align__(256) __half g_hid_h[B_N * H_N];
__device__ __align__(256) __half g_W_h[E_N * L_N * H_N];

__global__ void init_kernel() {
    int t = threadIdx.x;
    if (t < E_N) g_counts[t] = 0;
    if (t < 25)  g_pen[t]    = 0.0f;
    if (t == 0)  g_tile_ctr  = 0;
}

// ---------------- expert selection ----------------
__global__ void select_kernel(const float* __restrict__ envs,
                              const int* __restrict__ idx32,
                              const float* __restrict__ gumbel) {
    int b = blockIdx.x * blockDim.x + threadIdx.x;
    if (b >= B_N) return;
    int stride = (idx32[1] == 0) ? 2 : 1;   // int64-on-disk detection (idx = arange)
    int r = idx32[(size_t)b * stride];
    if (r < 0) r = 0;
    if (r >= B_N) r = B_N - 1;
    const float* ev = envs   + (size_t)r * E_N;
    const float* gv = gumbel + (size_t)b * E_N;
    float best = ev[0] + gv[0];
    int be = 0;
#pragma unroll
    for (int e = 1; e < E_N; e++) {
        float v = ev[e] + gv[e];
        if (v > best) { best = v; be = e; }
    }
    int pos = atomicAdd(&g_counts[be], 1);
    g_rows[be][pos] = b;
}

// ---------------- balanced tile list ----------------
// tile = (expert, 64-row m-chunk, 128-col l-block); enc = e<<12 | m<<4 | l
__global__ void build_tiles_kernel() {
    if (threadIdx.x == 0) {
        int n = 0;
        for (int e = 0; e < E_N; e++) {
            int mc = (g_counts[e] + 63) >> 6;
            for (int m = 0; m < mc; m++)
                for (int l = 0; l < 4; l++)
                    g_tiles[n++] = (e << 12) | (m << 4) | l;
        }
        g_ntiles = n;
    }
}

// ---------------- hidden -> fp16 ----------------
__global__ void __launch_bounds__(256)
convert_hidden_kernel(const float* __restrict__ hidden) {
    const int n4 = B_N * H_N / 4;
    const float4* hv = (const float4*)hidden;
    uint2* hh = (uint2*)g_hid_h;
    int stride = gridDim.x * blockDim.x;
    for (int i = blockIdx.x * blockDim.x + threadIdx.x; i < n4; i += stride) {
        float4 v = hv[i];
        __half2 h01 = __floats2half2_rn(v.x, v.y);
        __half2 h23 = __floats2half2_rn(v.z, v.w);
        uint2 p;
        p.x = *reinterpret_cast<uint32_t*>(&h01);
        p.y = *reinterpret_cast<uint32_t*>(&h23);
        hh[i] = p;
    }
}

// ---------------- penalty + W -> fp16 (fused single pass) ----------------
__global__ void __launch_bounds__(256)
penalty_kernel(const float* __restrict__ W) {
    const int LH4 = (L_N * H_N) / 4;
    const float4* Wv = (const float4*)W;
    uint2* wh = (uint2*)g_W_h;

    float q[8], c[8], l1[8], ss = 0.0f;
#pragma unroll
    for (int e = 0; e < 8; e++) { q[e] = 0.f; c[e] = 0.f; l1[e] = 0.f; }

    int stride = gridDim.x * blockDim.x;
    for (int i = blockIdx.x * blockDim.x + threadIdx.x; i < LH4; i += stride) {
        float4 w[8];
#pragma unroll
        for (int e = 0; e < 8; e++) w[e] = Wv[(size_t)e * LH4 + i];
#pragma unroll
        for (int e = 0; e < 8; e++) {
            float4 v = w[e];
            __half2 h01 = __floats2half2_rn(v.x, v.y);
            __half2 h23 = __floats2half2_rn(v.z, v.w);
            uint2 p;
            p.x = *reinterpret_cast<uint32_t*>(&h01);
            p.y = *reinterpret_cast<uint32_t*>(&h23);
            wh[(size_t)e * LH4 + i] = p;
        }
#pragma unroll
        for (int comp = 0; comp < 4; comp++) {
            float we[8];
#pragma unroll
            for (int e = 0; e < 8; e++) {
                float4 t = w[e];
                we[e] = (comp == 0) ? t.x : (comp == 1) ? t.y : (comp == 2) ? t.z : t.w;
            }
            float s = 0.f;
#pragma unroll
            for (int e = 0; e < 8; e++) s += we[e];
            ss = fmaf(s, s, ss);
#pragma unroll
            for (int e = 0; e < 8; e++) {
                q[e]  = fmaf(we[e], we[e], q[e]);
                c[e]  = fmaf(we[e], s,     c[e]);
                l1[e] += fabsf(we[e]);
            }
        }
    }

    __shared__ float red[25][264];
    int tid = threadIdx.x;
#pragma unroll
    for (int e = 0; e < 8; e++) {
        red[e][tid]      = q[e];
        red[8 + e][tid]  = c[e];
        red[16 + e][tid] = l1[e];
    }
    red[24][tid] = ss;
    __syncthreads();
    if (tid < 25) {
        float s = 0.f;
#pragma unroll 8
        for (int j = 0; j < 256; j++) s += red[tid][j];
        atomicAdd(&g_pen[tid], s);
    }
}

__global__ void finalize_kernel(float* __restrict__ pen_out) {
    if (threadIdx.x == 0) {
        float acc = 0.f;
        float ss = g_pen[24];
#pragma unroll
        for (int e = 0; e < 8; e++) {
            float diff = g_pen[e] - 0.25f * g_pen[8 + e] + ss * (1.0f / 64.0f);
            float l1 = g_pen[16 + e];
            acc += diff / (l1 * l1);
        }
        pen_out[0] = acc * 0.125f;
    }
}

// ====== persistent fp16 tensor-core grouped GEMM (balanced tile queue) ======
// CTA tile 64(M) x 128(N) x 64(K); 128 threads = 4 warps (2M x 2N), warp 32x64.
// Stage (bytes): A 8K | B 16K = 24KB; 3 stages = 72KB; 2 CTA/SM.
// Swizzle: row stride 64 halves (128B), 16B chunk phys = chunk ^ (row & 7).

#define TMB 64
#define TNB 128
#define TK 64
#define NSTAGE 3
#define STG_B 24576
#define NIT (H_N / TK)          // 64
#define SMEM_DYN (NSTAGE * STG_B + 1024)
#define GRID_GEMM 296

static __device__ __forceinline__ uint32_t s2u(const void* p) {
    return (uint32_t)__cvta_generic_to_shared(p);
}
static __device__ __forceinline__ void cp16(uint32_t s, const __half* g, bool pred) {
    int sz = pred ? 16 : 0;
    asm volatile("cp.async.cg.shared.global [%0], [%1], 16, %2;"
                 :: "r"(s), "l"(g), "r"(sz));
}

#define LDSM4(r0, r1, r2, r3, a) \
    asm volatile("ldmatrix.sync.aligned.m8n8.x4.shared.b16 {%0,%1,%2,%3}, [%4];" \
                 : "=r"(r0), "=r"(r1), "=r"(r2), "=r"(r3) : "r"(a))

#define MMAF16(d, A, b0, b1) \
    asm volatile("mma.sync.aligned.m16n8k16.row.col.f32.f16.f16.f32 " \
                 "{%0,%1,%2,%3}, {%4,%5,%6,%7}, {%8,%9}, {%0,%1,%2,%3};" \
                 : "+f"((d)[0]), "+f"((d)[1]), "+f"((d)[2]), "+f"((d)[3]) \
                 : "r"((A)[0]), "r"((A)[1]), "r"((A)[2]), "r"((A)[3]), \
                   "r"(b0), "r"(b1))

extern __shared__ char dyn_raw[];

__global__ void __launch_bounds__(128, 2)
gemm_kernel(float* __restrict__ out) {
    __shared__ int rowids[TMB];
    __shared__ int s_tile;

    int tid = threadIdx.x;
    int wid = tid >> 5, lane = tid & 31;

    uint32_t sbase = (s2u(dyn_raw) + 1023) & ~1023u;
    uint32_t stb[NSTAGE];
#pragma unroll
    for (int s = 0; s < NSTAGE; s++) stb[s] = sbase + s * STG_B;

    // loader geometry: 16B chunks; A 512 slots (4/thr), B 1024 slots (8/thr)
    int lrow = tid >> 3;              // 0..15
    int lcc  = tid & 7;
    int lphys = lcc ^ (lrow & 7);     // row&7 invariant (slots step rows by 16)
    int sOffA[4], sOffB[8];
#pragma unroll
    for (int i = 0; i < 4; i++) sOffA[i] = ((lrow + i * 16) * 64 + lphys * 8) * 2;
#pragma unroll
    for (int i = 0; i < 8; i++) sOffB[i] = ((lrow + i * 16) * 64 + lphys * 8) * 2;

    // warp geometry (32x64 warp tile): wm 2 x wn 2
    int wm = (wid & 1) * 32;
    int wn = (wid >> 1) * 64;
    int a_r = lane & 15, a_h = lane >> 4;
    int b_g = lane >> 3, b_sub = b_g >> 1, b_h = b_g & 1, b_r = lane & 7;

    int arow[2], axr[2];
#pragma unroll
    for (int mt = 0; mt < 2; mt++) {
        int r = wm + mt * 16 + a_r;
        arow[mt] = r * 64; axr[mt] = r & 7;
    }
    int brow[4], bxr[4];
#pragma unroll
    for (int p = 0; p < 4; p++) {
        int r = wn + p * 16 + b_sub * 8 + b_r;
        brow[p] = r * 64; bxr[p] = r & 7;
    }
    int gid = lane >> 2, tig = lane & 3;

    for (;;) {
        __syncthreads();   // previous tile fully done
        if (tid == 0) s_tile = atomicAdd(&g_tile_ctr, 1);
        __syncthreads();
        int t = s_tile;
        if (t >= g_ntiles) break;

        uint32_t enc = g_tiles[t];
        int e = enc >> 12;
        int mch = (enc >> 4) & 255;
        int l_base = (enc & 15) * TNB;
        int cnt = g_counts[e];

        if (tid < TMB) {
            int i = mch * TMB + tid;
            rowids[tid] = (i < cnt) ? g_rows[e][i] : -1;
        }
        __syncthreads();

        const __half* gA[4];
        const __half* gB[8];
        bool apred[4];
#pragma unroll
        for (int i = 0; i < 4; i++) {
            int row = lrow + i * 16;
            int g = rowids[row];
            apred[i] = (g >= 0);
            gA[i] = g_hid_h + (size_t)(apred[i] ? g : 0) * H_N + lcc * 8;
        }
#pragma unroll
        for (int i = 0; i < 8; i++) {
            int row = lrow + i * 16;
            gB[i] = g_W_h + ((size_t)e * L_N + l_base + row) * H_N + lcc * 8;
        }

        float acc[2][8][4];
#pragma unroll
        for (int mt = 0; mt < 2; mt++)
#pragma unroll
            for (int nt = 0; nt < 8; nt++)
#pragma unroll
                for (int j = 0; j < 4; j++) acc[mt][nt][j] = 0.f;

        // preload stages 0,1
#pragma unroll
        for (int p = 0; p < 2; p++) {
            uint32_t b = stb[p];
            int koff = p * TK;
#pragma unroll
            for (int i = 0; i < 4; i++) cp16(b + sOffA[i], gA[i] + koff, apred[i]);
#pragma unroll
            for (int i = 0; i < 8; i++) cp16(b + 8192 + sOffB[i], gB[i] + koff, true);
            asm volatile("cp.async.commit_group;");
        }

        int cur = 0, nxt = 2;
        for (int it = 0; it < NIT; it++) {
            asm volatile("cp.async.wait_group 1;");
            __syncthreads();

            int nc = it + 2;
            if (nc < NIT) {
                uint32_t b = stb[nxt];
                int koff = nc * TK;
#pragma unroll
                for (int i = 0; i < 4; i++) cp16(b + sOffA[i], gA[i] + koff, apred[i]);
#pragma unroll
                for (int i = 0; i < 8; i++) cp16(b + 8192 + sOffB[i], gB[i] + koff, true);
            }
            asm volatile("cp.async.commit_group;");

            uint32_t AS = stb[cur];
            uint32_t BS = AS + 8192;

#pragma unroll
            for (int s4 = 0; s4 < 4; s4++) {
                uint32_t af[2][4], bf[8][2];
#pragma unroll
                for (int mt = 0; mt < 2; mt++) {
                    int ch = (2 * s4 + a_h) ^ axr[mt];
                    LDSM4(af[mt][0], af[mt][1], af[mt][2], af[mt][3],
                          AS + (arow[mt] + ch * 8) * 2);
                }
#pragma unroll
                for (int p = 0; p < 4; p++) {
                    int ch = (2 * s4 + b_h) ^ bxr[p];
                    uint32_t r0, r1, r2, r3;
                    LDSM4(r0, r1, r2, r3, BS + (brow[p] + ch * 8) * 2);
                    bf[2 * p][0] = r0; bf[2 * p][1] = r1;
                    bf[2 * p + 1][0] = r2; bf[2 * p + 1][1] = r3;
                }
                // 16 independent MMAs (each acc touched once per s4)
#pragma unroll
                for (int mt = 0; mt < 2; mt++)
#pragma unroll
                    for (int nt = 0; nt < 8; nt++)
                        MMAF16(acc[mt][nt], af[mt], bf[nt][0], bf[nt][1]);
            }
            cur = (cur + 1 == NSTAGE) ? 0 : cur + 1;
            nxt = (nxt + 1 == NSTAGE) ? 0 : nxt + 1;
        }

        // ---- epilogue ----
#pragma unroll
        for (int mt = 0; mt < 2; mt++) {
            int r0 = wm + mt * 16 + gid;
            int r1 = r0 + 8;
            int g0 = rowids[r0];
            int g1 = rowids[r1];
#pragma unroll
            for (int nt = 0; nt < 8; nt++) {
                int col = l_base + wn + nt * 8 + tig * 2;
                if (g0 >= 0)
                    *(float2*)(out + (size_t)g0 * L_N + col) =
                        make_float2(acc[mt][nt][0], acc[mt][nt][1]);
                if (g1 >= 0)
                    *(float2*)(out + (size_t)g1 * L_N + col) =
                        make_float2(acc[mt][nt][2], acc[mt][nt][3]);
            }
        }
    }
}

// ---------------- launch ----------------
extern "C" void kernel_launch(void* const* d_in, const int* in_sizes, int n_in,
                              void* d_out, int out_size) {
    const float* hidden = (const float*)d_in[0];
    const float* envs   = (const float*)d_in[1];
    const int*   idx32  = (const int*)d_in[2];
    const float* gumbel = (const float*)d_in[3];
    const float* W      = (const float*)d_in[4];
    float* out = (float*)d_out;

    cudaFuncSetAttribute(gemm_kernel,
                         cudaFuncAttributeMaxDynamicSharedMemorySize, SMEM_DYN);

    init_kernel<<<1, 32>>>();
    select_kernel<<<(B_N + 255) / 256, 256>>>(envs, idx32, gumbel);
    build_tiles_kernel<<<1, 32>>>();
    convert_hidden_kernel<<<1024, 256>>>(hidden);
    penalty_kernel<<<512, 256>>>(W);

    gemm_kernel<<<GRID_GEMM, 128, SMEM_DYN>>>(out);

    if (out_size > B_N * L_N)
        finalize_kernel<<<1, 32>>>(out + (size_t)B_N * L_N);
}

// round 11
// speedup vs baseline: 2.4729x; 1.2391x over previous
#include <cuda_runtime.h>
#include <cuda_fp16.h>
#include <cstdint>

#define B_N 2048
#define H_N 4096
#define E_N 8
#define L_N 512

// ---------------- scratch ----------------
__device__ int   g_counts[E_N];
__device__ int   g_rows[E_N][B_N];
__device__ float g_pen[25];
__device__ int   g_ntiles;
__device__ int   g_tile_ctr;
__device__ uint32_t g_tiles[512];

__device__ __align__(256) __half g_hid_h[B_N * H_N];
__device__ __align__(256) __half g_W_h[E_N * L_N * H_N];

__global__ void init_kernel() {
    int t = threadIdx.x;
    if (t < E_N) g_counts[t] = 0;
    if (t < 25)  g_pen[t]    = 0.0f;
    if (t == 0)  g_tile_ctr  = 0;
}

// ---------------- expert selection ----------------
__global__ void select_kernel(const float* __restrict__ envs,
                              const int* __restrict__ idx32,
                              const float* __restrict__ gumbel) {
    int b = blockIdx.x * blockDim.x + threadIdx.x;
    if (b >= B_N) return;
    int stride = (idx32[1] == 0) ? 2 : 1;   // int64-on-disk detection (idx = arange)
    int r = idx32[(size_t)b * stride];
    if (r < 0) r = 0;
    if (r >= B_N) r = B_N - 1;
    const float* ev = envs   + (size_t)r * E_N;
    const float* gv = gumbel + (size_t)b * E_N;
    float best = ev[0] + gv[0];
    int be = 0;
#pragma unroll
    for (int e = 1; e < E_N; e++) {
        float v = ev[e] + gv[e];
        if (v > best) { best = v; be = e; }
    }
    int pos = atomicAdd(&g_counts[be], 1);
    g_rows[be][pos] = b;
}

// ---------------- balanced tile list ----------------
// tile = (expert, 64-row m-chunk, 128-col l-block); enc = e<<12 | m<<4 | l
__global__ void build_tiles_kernel() {
    if (threadIdx.x == 0) {
        int n = 0;
        for (int e = 0; e < E_N; e++) {
            int mc = (g_counts[e] + 63) >> 6;
            for (int m = 0; m < mc; m++)
                for (int l = 0; l < 4; l++)
                    g_tiles[n++] = (e << 12) | (m << 4) | l;
        }
        g_ntiles = n;
    }
}

// ---------------- hidden -> fp16 ----------------
__global__ void __launch_bounds__(256)
convert_hidden_kernel(const float* __restrict__ hidden) {
    const int n4 = B_N * H_N / 4;
    const float4* hv = (const float4*)hidden;
    uint2* hh = (uint2*)g_hid_h;
    int stride = gridDim.x * blockDim.x;
    for (int i = blockIdx.x * blockDim.x + threadIdx.x; i < n4; i += stride) {
        float4 v = hv[i];
        __half2 h01 = __floats2half2_rn(v.x, v.y);
        __half2 h23 = __floats2half2_rn(v.z, v.w);
        uint2 p;
        p.x = *reinterpret_cast<uint32_t*>(&h01);
        p.y = *reinterpret_cast<uint32_t*>(&h23);
        hh[i] = p;
    }
}

// ------- penalty + W -> fp16, double-buffered single pass -------
// grid*block must divide LH4: 1024 * 128 = 131072; LH4 = 524288 -> 4 iters.
#define PEN_GRID 1024
#define PEN_BLK  128

__global__ void __launch_bounds__(PEN_BLK, 4)
penalty_kernel(const float* __restrict__ W) {
    const int LH4 = (L_N * H_N) / 4;
    const float4* Wv = (const float4*)W;
    uint2* wh = (uint2*)g_W_h;
    const int stride = PEN_GRID * PEN_BLK;
    const int iters = LH4 / stride;   // 4

    float q[8], c[8], l1[8], ss = 0.0f;
#pragma unroll
    for (int e = 0; e < 8; e++) { q[e] = 0.f; c[e] = 0.f; l1[e] = 0.f; }

    int i = blockIdx.x * PEN_BLK + threadIdx.x;

    float4 buf[8];
#pragma unroll
    for (int e = 0; e < 8; e++) buf[e] = Wv[(size_t)e * LH4 + i];

    for (int it = 0; it < iters; it++) {
        float4 nxt[8];
        int i2 = i + stride;
        if (it + 1 < iters) {
#pragma unroll
            for (int e = 0; e < 8; e++) nxt[e] = Wv[(size_t)e * LH4 + i2];
        }
        // convert + store fp16
#pragma unroll
        for (int e = 0; e < 8; e++) {
            float4 v = buf[e];
            __half2 h01 = __floats2half2_rn(v.x, v.y);
            __half2 h23 = __floats2half2_rn(v.z, v.w);
            uint2 p;
            p.x = *reinterpret_cast<uint32_t*>(&h01);
            p.y = *reinterpret_cast<uint32_t*>(&h23);
            wh[(size_t)e * LH4 + i] = p;
        }
        // stats
#pragma unroll
        for (int comp = 0; comp < 4; comp++) {
            float we[8];
#pragma unroll
            for (int e = 0; e < 8; e++) {
                float4 t = buf[e];
                we[e] = (comp == 0) ? t.x : (comp == 1) ? t.y : (comp == 2) ? t.z : t.w;
            }
            float s = 0.f;
#pragma unroll
            for (int e = 0; e < 8; e++) s += we[e];
            ss = fmaf(s, s, ss);
#pragma unroll
            for (int e = 0; e < 8; e++) {
                q[e]  = fmaf(we[e], we[e], q[e]);
                c[e]  = fmaf(we[e], s,     c[e]);
                l1[e] += fabsf(we[e]);
            }
        }
        if (it + 1 < iters) {
#pragma unroll
            for (int e = 0; e < 8; e++) buf[e] = nxt[e];
            i = i2;
        }
    }

    __shared__ float red[25][136];
    int tid = threadIdx.x;
#pragma unroll
    for (int e = 0; e < 8; e++) {
        red[e][tid]      = q[e];
        red[8 + e][tid]  = c[e];
        red[16 + e][tid] = l1[e];
    }
    red[24][tid] = ss;
    __syncthreads();
    if (tid < 25) {
        float s = 0.f;
#pragma unroll 8
        for (int j = 0; j < PEN_BLK; j++) s += red[tid][j];
        atomicAdd(&g_pen[tid], s);
    }
}

__global__ void finalize_kernel(float* __restrict__ pen_out) {
    if (threadIdx.x == 0) {
        float acc = 0.f;
        float ss = g_pen[24];
#pragma unroll
        for (int e = 0; e < 8; e++) {
            float diff = g_pen[e] - 0.25f * g_pen[8 + e] + ss * (1.0f / 64.0f);
            float l1 = g_pen[16 + e];
            acc += diff / (l1 * l1);
        }
        pen_out[0] = acc * 0.125f;
    }
}

// ====== persistent fp16 tensor-core grouped GEMM (1 CTA/SM) ======
// CTA tile 64(M) x 128(N) x 64(K); 256 threads = 8 warps (2M x 4N), warp 32x32.
// Stage (bytes): A 8K | B 16K = 24KB; 4 stages = 96KB.
// Swizzle: row stride 64 halves (128B), 16B chunk phys = chunk ^ (row & 7).

#define TMB 64
#define TNB 128
#define TK 64
#define NSTAGE 4
#define STG_B 24576
#define NIT (H_N / TK)          // 64
#define SMEM_DYN (NSTAGE * STG_B + 1024)
#define GRID_GEMM 148

static __device__ __forceinline__ uint32_t s2u(const void* p) {
    return (uint32_t)__cvta_generic_to_shared(p);
}
static __device__ __forceinline__ void cp16(uint32_t s, const __half* g, bool pred) {
    int sz = pred ? 16 : 0;
    asm volatile("cp.async.cg.shared.global [%0], [%1], 16, %2;"
                 :: "r"(s), "l"(g), "r"(sz));
}

#define LDSM4(r0, r1, r2, r3, a) \
    asm volatile("ldmatrix.sync.aligned.m8n8.x4.shared.b16 {%0,%1,%2,%3}, [%4];" \
                 : "=r"(r0), "=r"(r1), "=r"(r2), "=r"(r3) : "r"(a))

#define MMAF16(d, A, b0, b1) \
    asm volatile("mma.sync.aligned.m16n8k16.row.col.f32.f16.f16.f32 " \
                 "{%0,%1,%2,%3}, {%4,%5,%6,%7}, {%8,%9}, {%0,%1,%2,%3};" \
                 : "+f"((d)[0]), "+f"((d)[1]), "+f"((d)[2]), "+f"((d)[3]) \
                 : "r"((A)[0]), "r"((A)[1]), "r"((A)[2]), "r"((A)[3]), \
                   "r"(b0), "r"(b1))

extern __shared__ char dyn_raw[];

__global__ void __launch_bounds__(256, 1)
gemm_kernel(float* __restrict__ out) {
    __shared__ int rowids[TMB];
    __shared__ int s_tile;

    int tid = threadIdx.x;
    int wid = tid >> 5, lane = tid & 31;

    uint32_t sbase = (s2u(dyn_raw) + 1023) & ~1023u;
    uint32_t stb[NSTAGE];
#pragma unroll
    for (int s = 0; s < NSTAGE; s++) stb[s] = sbase + s * STG_B;

    // loader geometry: 16B chunks; A 512 slots (2/thr), B 1024 slots (4/thr)
    int lrow = tid >> 3;              // 0..31
    int lcc  = tid & 7;
    int lphys = lcc ^ (lrow & 7);     // row&7 invariant (rows step by 32)
    int sOffA[2], sOffB[4];
#pragma unroll
    for (int i = 0; i < 2; i++) sOffA[i] = ((lrow + i * 32) * 64 + lphys * 8) * 2;
#pragma unroll
    for (int i = 0; i < 4; i++) sOffB[i] = ((lrow + i * 32) * 64 + lphys * 8) * 2;

    // warp geometry (32x32 warp tile): 2 warps on M, 4 on N
    int wm = (wid & 1) * 32;
    int wn = (wid >> 1) * 32;
    int a_r = lane & 15, a_h = lane >> 4;
    int b_g = lane >> 3, b_sub = b_g >> 1, b_h = b_g & 1, b_r = lane & 7;

    int arow[2], axr[2];
#pragma unroll
    for (int mt = 0; mt < 2; mt++) {
        int r = wm + mt * 16 + a_r;
        arow[mt] = r * 64; axr[mt] = r & 7;
    }
    int brow[2], bxr[2];
#pragma unroll
    for (int p = 0; p < 2; p++) {
        int r = wn + p * 16 + b_sub * 8 + b_r;
        brow[p] = r * 64; bxr[p] = r & 7;
    }
    int gid = lane >> 2, tig = lane & 3;

    for (;;) {
        __syncthreads();   // previous tile fully done
        if (tid == 0) s_tile = atomicAdd(&g_tile_ctr, 1);
        __syncthreads();
        int t = s_tile;
        if (t >= g_ntiles) break;

        uint32_t enc = g_tiles[t];
        int e = enc >> 12;
        int mch = (enc >> 4) & 255;
        int l_base = (enc & 15) * TNB;
        int cnt = g_counts[e];

        if (tid < TMB) {
            int i = mch * TMB + tid;
            rowids[tid] = (i < cnt) ? g_rows[e][i] : -1;
        }
        __syncthreads();

        const __half* gA[2];
        const __half* gB[4];
        bool apred[2];
#pragma unroll
        for (int i = 0; i < 2; i++) {
            int row = lrow + i * 32;
            int g = rowids[row];
            apred[i] = (g >= 0);
            gA[i] = g_hid_h + (size_t)(apred[i] ? g : 0) * H_N + lcc * 8;
        }
#pragma unroll
        for (int i = 0; i < 4; i++) {
            int row = lrow + i * 32;
            gB[i] = g_W_h + ((size_t)e * L_N + l_base + row) * H_N + lcc * 8;
        }

        float acc[2][4][4];
#pragma unroll
        for (int mt = 0; mt < 2; mt++)
#pragma unroll
            for (int nt = 0; nt < 4; nt++)
#pragma unroll
                for (int j = 0; j < 4; j++) acc[mt][nt][j] = 0.f;

        // preload stages 0..2
#pragma unroll
        for (int p = 0; p < NSTAGE - 1; p++) {
            uint32_t b = stb[p];
            int koff = p * TK;
#pragma unroll
            for (int i = 0; i < 2; i++) cp16(b + sOffA[i], gA[i] + koff, apred[i]);
#pragma unroll
            for (int i = 0; i < 4; i++) cp16(b + 8192 + sOffB[i], gB[i] + koff, true);
            asm volatile("cp.async.commit_group;");
        }

        int cur = 0, nxt = NSTAGE - 1;
        for (int it = 0; it < NIT; it++) {
            asm volatile("cp.async.wait_group 2;");
            __syncthreads();

            int nc = it + NSTAGE - 1;
            if (nc < NIT) {
                uint32_t b = stb[nxt];
                int koff = nc * TK;
#pragma unroll
                for (int i = 0; i < 2; i++) cp16(b + sOffA[i], gA[i] + koff, apred[i]);
#pragma unroll
                for (int i = 0; i < 4; i++) cp16(b + 8192 + sOffB[i], gB[i] + koff, true);
            }
            asm volatile("cp.async.commit_group;");

            uint32_t AS = stb[cur];
            uint32_t BS = AS + 8192;

#pragma unroll
            for (int s4 = 0; s4 < 4; s4++) {
                uint32_t af[2][4], bf[4][2];
#pragma unroll
                for (int mt = 0; mt < 2; mt++) {
                    int ch = (2 * s4 + a_h) ^ axr[mt];
                    LDSM4(af[mt][0], af[mt][1], af[mt][2], af[mt][3],
                          AS + (arow[mt] + ch * 8) * 2);
                }
#pragma unroll
                for (int p = 0; p < 2; p++) {
                    int ch = (2 * s4 + b_h) ^ bxr[p];
                    uint32_t r0, r1, r2, r3;
                    LDSM4(r0, r1, r2, r3, BS + (brow[p] + ch * 8) * 2);
                    bf[2 * p][0] = r0; bf[2 * p][1] = r1;
                    bf[2 * p + 1][0] = r2; bf[2 * p + 1][1] = r3;
                }
                // 8 independent MMAs (each acc touched once per s4)
#pragma unroll
                for (int mt = 0; mt < 2; mt++)
#pragma unroll
                    for (int nt = 0; nt < 4; nt++)
                        MMAF16(acc[mt][nt], af[mt], bf[nt][0], bf[nt][1]);
            }
            cur = (cur + 1 == NSTAGE) ? 0 : cur + 1;
            nxt = (nxt + 1 == NSTAGE) ? 0 : nxt + 1;
        }

        // ---- epilogue ----
#pragma unroll
        for (int mt = 0; mt < 2; mt++) {
            int r0 = wm + mt * 16 + gid;
            int r1 = r0 + 8;
            int g0 = rowids[r0];
            int g1 = rowids[r1];
#pragma unroll
            for (int nt = 0; nt < 4; nt++) {
                int col = l_base + wn + nt * 8 + tig * 2;
                if (g0 >= 0)
                    *(float2*)(out + (size_t)g0 * L_N + col) =
                        make_float2(acc[mt][nt][0], acc[mt][nt][1]);
                if (g1 >= 0)
                    *(float2*)(out + (size_t)g1 * L_N + col) =
                        make_float2(acc[mt][nt][2], acc[mt][nt][3]);
            }
        }
    }
}

// ---------------- launch ----------------
extern "C" void kernel_launch(void* const* d_in, const int* in_sizes, int n_in,
                              void* d_out, int out_size) {
    const float* hidden = (const float*)d_in[0];
    const float* envs   = (const float*)d_in[1];
    const int*   idx32  = (const int*)d_in[2];
    const float* gumbel = (const float*)d_in[3];
    const float* W      = (const float*)d_in[4];
    float* out = (float*)d_out;

    cudaFuncSetAttribute(gemm_kernel,
                         cudaFuncAttributeMaxDynamicSharedMemorySize, SMEM_DYN);

    init_kernel<<<1, 32>>>();
    select_kernel<<<(B_N + 255) / 256, 256>>>(envs, idx32, gumbel);
    build_tiles_kernel<<<1, 32>>>();
    convert_hidden_kernel<<<1024, 256>>>(hidden);
    penalty_kernel<<<PEN_GRID, PEN_BLK>>>(W);

    gemm_kernel<<<GRID_GEMM, 256, SMEM_DYN>>>(out);

    if (out_size > B_N * L_N)
        finalize_kernel<<<1, 32>>>(out + (size_t)B_N * L_N);
}